// round 15
// baseline (speedup 1.0000x reference)
#include <cuda_runtime.h>
#include <cuda_fp16.h>

#define Bb   128
#define DIN  512
#define HH   1024
#define G4   4096
#define TT   256
#define OO   1024
#define BH   (Bb*HH)
#define NBLK 128
#define NTHR 256
#define SLOT 262144   // per-step h slot: 16 chunks x 16KB (fp16 single plane)

// ---- device-global scratch ----
__device__ __align__(16) unsigned char g_hT[(TT+1)*SLOT];   // h history, tiled fp16
__device__ __align__(16) float         g_c0[BH];            // initial cell state
__device__ __align__(16) unsigned char g_WswF[NBLK*65536];  // folded slices, fp16 (t>=1)
__device__ __align__(16) unsigned char g_Wsw0[NBLK*65536];  // W_hh slices, fp16 (t==0)
__device__ __align__(16) unsigned char g_WoS[NBLK*16384];   // W_out slices (8 rows/CTA), fp16
__device__ float    g_bF[G4];
__device__ float    g_b0[G4];
__device__ unsigned g_bar[TT];                              // monotonic barrier counters

__device__ __forceinline__ float sigf(float x) { return 1.0f / (1.0f + __expf(-x)); }

__device__ __forceinline__ unsigned smem_u32(const void* p) {
    return (unsigned)__cvta_generic_to_shared(p);
}
__device__ __forceinline__ void ldsm4(unsigned* r, unsigned addr) {
    asm volatile("ldmatrix.sync.aligned.m8n8.x4.shared.b16 {%0,%1,%2,%3}, [%4];"
                 : "=r"(r[0]), "=r"(r[1]), "=r"(r[2]), "=r"(r[3]) : "r"(addr));
}
__device__ __forceinline__ void ldsm2(unsigned* r, unsigned addr) {
    asm volatile("ldmatrix.sync.aligned.m8n8.x2.shared.b16 {%0,%1}, [%2];"
                 : "=r"(r[0]), "=r"(r[1]) : "r"(addr));
}
__device__ __forceinline__ void mma16816(float* d, const unsigned* a, const unsigned* b) {
    asm volatile("mma.sync.aligned.m16n8k16.row.col.f32.f16.f16.f32 "
                 "{%0,%1,%2,%3}, {%4,%5,%6,%7}, {%8,%9}, {%0,%1,%2,%3};"
                 : "+f"(d[0]), "+f"(d[1]), "+f"(d[2]), "+f"(d[3])
                 : "r"(a[0]), "r"(a[1]), "r"(a[2]), "r"(a[3]), "r"(b[0]), "r"(b[1]));
}
__device__ __forceinline__ void cpasync16(unsigned saddr, const void* g) {
    asm volatile("cp.async.cg.shared.global [%0], [%1], 16;" :: "r"(saddr), "l"(g));
}
__device__ __forceinline__ void cpcommit() { asm volatile("cp.async.commit_group;" ::: "memory"); }
template<int N> __device__ __forceinline__ void cpwait() {
    asm volatile("cp.async.wait_group %0;" :: "n"(N) : "memory");
}
__device__ __forceinline__ unsigned pk_h2(float a, float b) {
    return (unsigned)__half_as_ushort(__float2half_rn(a))
         | ((unsigned)__half_as_ushort(__float2half_rn(b)) << 16);
}
__device__ __forceinline__ unsigned pkh2f(float a, float b) {
    __half2 h = __floats2half2_rn(a, b);
    return *(unsigned*)&h;
}

// ---------------------------------------------------------------------------
// k_pre: fused prologue. Block ranges:
//   [0, 4096)       foldw (x4 vectorized) — W_ih+W_hh -> g_WswF, W_hh -> g_Wsw0
//   [4096, 5120)    foldo (x4 vectorized) — W_out -> g_WoS per-CTA 8-row slices
//   [5120, 5632)    bias  — g_bF / g_b0 (x0-folded)
//   [5632, 5760)    init  — h0 (fp16 tiled) + c0; 128 blocks x 8 units
// ---------------------------------------------------------------------------
__global__ void __launch_bounds__(256) k_pre(
    const float* __restrict__ z,
    const float* __restrict__ Wfch, const float* __restrict__ bfch,
    const float* __restrict__ Wfcc, const float* __restrict__ bfcc,
    const float* __restrict__ Wih,  const float* __restrict__ bih,
    const float* __restrict__ Whh,  const float* __restrict__ bhh,
    const float* __restrict__ x0,   const float* __restrict__ Wout)
{
    __shared__ float zs[128][33];
    __shared__ float Whs[8][33];
    __shared__ float Wcs[8][33];
    const int tid = threadIdx.x;
    const int blk = blockIdx.x;

    if (blk < 4096) {
        // ---- foldw, 4 consecutive k per thread ----
        int i = blk * 256 + tid;                          // 1,048,576
        int k4 = (i & 255) << 2, rr = (i >> 8) & 31, bx = i >> 13;
        int gate = rr >> 3, unit = rr & 7;
        int j = (gate << 10) + (bx << 3) + unit;
        float4 a4 = *(const float4*)(Wih + (size_t)j * HH + k4);
        float4 b4 = *(const float4*)(Whh + (size_t)j * HH + k4);
        int off = ((k4 >> 4) << 10) + (((gate << 1) + ((k4 >> 3) & 1)) << 7)
                + (unit << 4) + ((k4 & 7) << 1);
        uint2 vf, v0;
        vf.x = pkh2f(a4.x + b4.x, a4.y + b4.y);
        vf.y = pkh2f(a4.z + b4.z, a4.w + b4.w);
        v0.x = pkh2f(b4.x, b4.y);
        v0.y = pkh2f(b4.z, b4.w);
        *(uint2*)(g_WswF + (size_t)bx * 65536 + off) = vf;
        *(uint2*)(g_Wsw0 + (size_t)bx * 65536 + off) = v0;
    } else if (blk < 5120) {
        // ---- foldo: W_out row o -> slice (o>>3), layout [ckk(64)][kt(2)][8x16B] ----
        int i = (blk - 4096) * 256 + tid;                 // 262,144
        int k4 = (i & 255) << 2, o = i >> 8;
        int bx = o >> 3, r = o & 7;
        float4 w4 = *(const float4*)(Wout + (size_t)o * HH + k4);
        int off = ((k4 >> 4) << 8) + (((k4 >> 3) & 1) << 7) + (r << 4) + ((k4 & 7) << 1);
        uint2 v;
        v.x = pkh2f(w4.x, w4.y);
        v.y = pkh2f(w4.z, w4.w);
        *(uint2*)(g_WoS + (size_t)bx * 16384 + off) = v;
    } else if (blk < 5632) {
        // ---- bias ----
        int w    = ((blk - 5120) * 256 + tid) >> 5;
        int lane = tid & 31;
        int bx = w >> 5, lr = w & 31;
        int j  = (bx << 3) + (lr & 7) + ((lr >> 3) << 10);
        float s = 0.f;
        for (int k = lane; k < HH; k += 32) s += x0[k] * Wih[(size_t)j * HH + k];
        #pragma unroll
        for (int off = 16; off; off >>= 1) s += __shfl_down_sync(0xffffffffu, s, off);
        if (lane == 0) {
            float bf = bih[j] + bhh[j];
            g_bF[w] = bf;
            g_b0[w] = bf + s;
        }
    } else {
        // ---- init: block bb handles units [bb*8, bb*8+8) for all 128 batches ----
        int bb = blk - 5632;                              // 0..127
        const int b = tid & 127, ug = tid >> 7;
        float accH[4], accC[4];
        #pragma unroll
        for (int j = 0; j < 4; ++j) { accH[j] = 0.f; accC[j] = 0.f; }

        for (int kc = 0; kc < 16; ++kc) {
            #pragma unroll
            for (int tq = 0; tq < 16; ++tq) {
                int idx = tid + tq * 256;
                int br = idx >> 5, kk = idx & 31;
                zs[br][kk] = z[br * DIN + kc * 32 + kk];
            }
            {
                int ur = tid >> 5, kk = tid & 31;
                Whs[ur][kk] = Wfch[(size_t)(bb * 8 + ur) * DIN + kc * 32 + kk];
                Wcs[ur][kk] = Wfcc[(size_t)(bb * 8 + ur) * DIN + kc * 32 + kk];
            }
            __syncthreads();
            #pragma unroll 8
            for (int kk = 0; kk < 32; ++kk) {
                float zv = zs[b][kk];
                #pragma unroll
                for (int j = 0; j < 4; ++j) {
                    accH[j] += zv * Whs[ug * 4 + j][kk];
                    accC[j] += zv * Wcs[ug * 4 + j][kk];
                }
            }
            __syncthreads();
        }

        #pragma unroll
        for (int j = 0; j < 4; ++j) {
            int u = bb * 8 + ug * 4 + j;
            float hv = accH[j] + bfch[u];
            int ck = u >> 6, C = u & 63;
            int off = (((b >> 3) << 3) + (C >> 3)) * 128 + ((b & 7) << 4) + ((C & 7) << 1);
            *(__half*)(g_hT + (size_t)ck * 16384 + off) = __float2half_rn(hv);
            g_c0[b * HH + u] = accC[j] + bfcc[u];
        }
    }
}

// ---------------------------------------------------------------------------
// Persistent HMMA recurrence WITH fused output projection.
// 128 CTAs x 8 warps. fp16 gate-W slice (64KB) + W_out slice (16KB) in SMEM.
// Loop t = 0..TT: stream h slot t; t<TT -> gate GEMM (-> h slot t+1);
// t>=1 -> out GEMM for row t-1 on the SAME streamed chunks, stored during the
// barrier wait. Iteration TT only drains the last output row.
// SMEM: 0 b0s |128 bFs |256 boS |512 so(4KB) |4608 W 64K |70144 WoS 16K |
//       ring 86528 + i*16384 (4 bufs)
// ---------------------------------------------------------------------------
#define S_W   4608
#define S_WO  70144
#define S_SO  512
#define S_TOT 152064

__global__ void __launch_bounds__(NTHR, 1) k_steps_mma(const float* __restrict__ bout,
                                                       float* __restrict__ out) {
    extern __shared__ unsigned char sm[];
    const unsigned sb = smem_u32(sm);
    const int tid = threadIdx.x, blk = blockIdx.x;
    const int w = tid >> 5, lane = tid & 31;
    const int q = lane & 3, gr = lane >> 2, ls = lane >> 3;
    float* b0s = (float*)(sm);
    float* bFs = (float*)(sm + 128);
    float* boS = (float*)(sm + 256);
    float* so  = (float*)(sm + S_SO);

    if (tid < 32) {
        b0s[tid] = g_b0[blk * 32 + tid];
        bFs[tid] = g_bF[blk * 32 + tid];
    }
    if (tid < 8) boS[tid] = bout[blk * 8 + tid];
    {   // gate-W slice for step 0 (W_hh only)
        const uint4* src = (const uint4*)(g_Wsw0 + (size_t)blk * 65536);
        uint4* dst = (uint4*)(sm + S_W);
        for (int i = tid; i < 4096; i += NTHR) dst[i] = src[i];
    }
    {   // W_out slice (resident all steps)
        const uint4* src = (const uint4*)(g_WoS + (size_t)blk * 16384);
        uint4* dst = (uint4*)(sm + S_WO);
        for (int i = tid; i < 1024; i += NTHR) dst[i] = src[i];
    }
    float cst[2][2];
    {
        int m0 = (w << 4) + gr;
        float2 v0 = *(const float2*)(g_c0 + m0 * HH + (blk << 3) + (q << 1));
        float2 v1 = *(const float2*)(g_c0 + (m0 + 8) * HH + (blk << 3) + (q << 1));
        cst[0][0] = v0.x; cst[0][1] = v0.y;
        cst[1][0] = v1.x; cst[1][1] = v1.y;
    }
    __syncthreads();

    const unsigned aBase = (unsigned)(((w * 2 + (ls & 1)) * 8 + (ls >> 1)) * 128 + (lane & 7) * 16);
    const unsigned bBase = (unsigned)((((ls >> 1) * 2 + (ls & 1)) * 128) + (lane & 7) * 16);
    const int al = lane & 15;
    const unsigned oBase = (unsigned)(((al >> 3) << 7) + ((al & 7) << 4));
    const int cpo = tid * 16;
    unsigned bufs[4] = {sb + 86528u, sb + 102912u, sb + 119296u, sb + 135680u};

    float accO[4];
    #pragma unroll
    for (int a = 0; a < 4; ++a) accO[a] = 0.f;

    for (int t = 0; t <= TT; ++t) {
        const unsigned char* hsrc = g_hT + (size_t)t * SLOT;

        // prologue: issue chunks 0,1,2
        #pragma unroll
        for (int c = 0; c < 3; ++c) {
            const unsigned char* src = hsrc + (size_t)c * 16384;
            #pragma unroll
            for (int j = 0; j < 4; ++j) cpasync16(bufs[c] + cpo + j * 4096, src + cpo + j * 4096);
            cpcommit();
        }

        float acc[4][4];
        #pragma unroll
        for (int a = 0; a < 4; ++a)
            #pragma unroll
            for (int b = 0; b < 4; ++b) acc[a][b] = 0.f;

        for (int i = 0; i < 16; ++i) {
            if (i <= 13) cpwait<2>(); else if (i == 14) cpwait<1>(); else cpwait<0>();
            __syncthreads();
            if (i < 13) {   // prefetch chunk i+3 into freed buffer
                const unsigned char* src = hsrc + (size_t)(i + 3) * 16384;
                unsigned buf = bufs[(i + 3) & 3];
                #pragma unroll
                for (int j = 0; j < 4; ++j) cpasync16(buf + cpo + j * 4096, src + cpo + j * 4096);
                cpcommit();
            }
            unsigned cur = bufs[i & 3];
            #pragma unroll
            for (int kk = 0; kk < 4; ++kk) {
                unsigned Ah[4];
                ldsm4(Ah, cur + aBase + kk * 256);
                int ckk = i * 4 + kk;
                if (t < TT) {
                    #pragma unroll
                    for (int gg = 0; gg < 2; ++gg) {
                        unsigned Bh[4];
                        ldsm4(Bh, sb + S_W + ckk * 1024 + gg * 512 + bBase);
                        mma16816(acc[2 * gg],     Ah, Bh);
                        mma16816(acc[2 * gg + 1], Ah, Bh + 2);
                    }
                }
                if (t >= 1) {
                    unsigned Bo[2];
                    ldsm2(Bo, sb + S_WO + ckk * 256 + oBase);
                    mma16816(accO, Ah, Bo);
                }
            }
        }

        if (t < TT) {
            // gate epilogue: 4 gates of (b, u) live in this thread
            const float* bs = t ? bFs : b0s;
            unsigned char* hd = g_hT + (size_t)(t + 1) * SLOT + (size_t)(blk >> 3) * 16384;
            const int cb = blk & 7;
            #pragma unroll
            for (int r = 0; r < 2; ++r) {
                float hv[2];
                #pragma unroll
                for (int s = 0; s < 2; ++s) {
                    int u = (q << 1) + s;
                    int fi = r * 2 + s;
                    float ig = acc[0][fi] + bs[u];
                    float fg = acc[1][fi] + bs[8 + u];
                    float gg = acc[2][fi] + bs[16 + u];
                    float og = acc[3][fi] + bs[24 + u];
                    float cn = sigf(fg) * cst[r][s] + sigf(ig) * tanhf(gg);
                    cst[r][s] = cn;
                    hv[s] = sigf(og) * tanhf(cn);
                }
                int toff = (((2 * w + r) << 3) + cb) * 128 + (gr << 4) + (q << 2);
                *(unsigned*)(hd + toff) = pk_h2(hv[0], hv[1]);
            }
        }

        __threadfence();
        __syncthreads();
        unsigned target = 0;
        if (t < TT && tid == 0) {   // post arrive early; spin later (out store overlaps)
            unsigned old;
            asm volatile("atom.release.gpu.global.add.u32 %0, [%1], %2;"
                         : "=r"(old) : "l"(&g_bar[t]), "r"(1u) : "memory");
            target = old - (old & (NBLK - 1)) + NBLK;
        }

        if (t >= 1) {
            // stage out row t-1 (bias + leaky applied here), then coalesced store
            #pragma unroll
            for (int r = 0; r < 2; ++r)
                #pragma unroll
                for (int c = 0; c < 2; ++c) {
                    int n = (q << 1) + c;
                    int b = (w << 4) + gr + (r << 3);
                    float x = accO[r * 2 + c] + boS[n];
                    so[b * 8 + n] = x >= 0.f ? x : 0.2f * x;
                }
            __syncthreads();
            if (tid < 128) {
                float4 v0 = *(float4*)(so + tid * 8);
                float4 v1 = *(float4*)(so + tid * 8 + 4);
                float* op = out + ((size_t)tid * TT + (t - 1)) * OO + blk * 8;
                *(float4*)op       = v0;
                *(float4*)(op + 4) = v1;
            }
            #pragma unroll
            for (int a = 0; a < 4; ++a) accO[a] = 0.f;
        }

        if (t < TT) {
            if (tid == 0) {
                unsigned v;
                do {
                    asm volatile("ld.acquire.gpu.global.u32 %0, [%1];"
                                 : "=r"(v) : "l"(&g_bar[t]) : "memory");
                } while ((int)(v - target) < 0);
            }
            __syncthreads();
        }

        if (t == 0) {   // swap in folded weights for steps >= 1
            const uint4* src = (const uint4*)(g_WswF + (size_t)blk * 65536);
            uint4* dst = (uint4*)(sm + S_W);
            for (int i2 = tid; i2 < 4096; i2 += NTHR) dst[i2] = src[i2];
            __syncthreads();
        }
    }
}

// ---------------------------------------------------------------------------
extern "C" void kernel_launch(void* const* d_in, const int* in_sizes, int n_in,
                              void* d_out, int out_size) {
    const float* z      = (const float*)d_in[0];
    const float* W_fc_h = (const float*)d_in[2];
    const float* b_fc_h = (const float*)d_in[3];
    const float* W_fc_c = (const float*)d_in[4];
    const float* b_fc_c = (const float*)d_in[5];
    const float* W_ih   = (const float*)d_in[6];
    const float* b_ih   = (const float*)d_in[7];
    const float* W_hh   = (const float*)d_in[8];
    const float* b_hh   = (const float*)d_in[9];
    const float* x0     = (const float*)d_in[10];
    const float* W_out  = (const float*)d_in[11];
    const float* b_out  = (const float*)d_in[12];
    float* out = (float*)d_out;

    k_pre<<<5760, 256>>>(z, W_fc_h, b_fc_h, W_fc_c, b_fc_c,
                         W_ih, b_ih, W_hh, b_hh, x0, W_out);

    cudaFuncSetAttribute(k_steps_mma, cudaFuncAttributeMaxDynamicSharedMemorySize, S_TOT);
    k_steps_mma<<<NBLK, NTHR, S_TOT>>>(b_out, out);
}

// round 16
// speedup vs baseline: 1.2221x; 1.2221x over previous
#include <cuda_runtime.h>
#include <cuda_fp16.h>

#define Bb   128
#define DIN  512
#define HH   1024
#define G4   4096
#define TT   256
#define OO   1024
#define BH   (Bb*HH)
#define NBLK 128
#define NTHR 256
#define SLOT 262144   // per-step h slot: 16 chunks x 16KB (fp16 single plane)

// ---- device-global scratch ----
__device__ __align__(16) unsigned char g_hT[(TT+1)*SLOT];   // h history, tiled fp16
__device__ __align__(16) float         g_c0[BH];            // initial cell state
__device__ __align__(16) unsigned char g_WswF[NBLK*65536];  // folded slices, fp16 (t>=1)
__device__ __align__(16) unsigned char g_Wsw0[NBLK*65536];  // W_hh slices, fp16 (t==0)
__device__ __align__(16) unsigned char g_WoT[16*16*8192];   // W_out tiles, fp16
__device__ float    g_bF[G4];
__device__ float    g_b0[G4];
__device__ unsigned g_bar[TT];                              // monotonic barrier counters

__device__ __forceinline__ float sigf(float x) { return 1.0f / (1.0f + __expf(-x)); }

__device__ __forceinline__ unsigned smem_u32(const void* p) {
    return (unsigned)__cvta_generic_to_shared(p);
}
__device__ __forceinline__ void ldsm4(unsigned* r, unsigned addr) {
    asm volatile("ldmatrix.sync.aligned.m8n8.x4.shared.b16 {%0,%1,%2,%3}, [%4];"
                 : "=r"(r[0]), "=r"(r[1]), "=r"(r[2]), "=r"(r[3]) : "r"(addr));
}
__device__ __forceinline__ void mma16816(float* d, const unsigned* a, const unsigned* b) {
    asm volatile("mma.sync.aligned.m16n8k16.row.col.f32.f16.f16.f32 "
                 "{%0,%1,%2,%3}, {%4,%5,%6,%7}, {%8,%9}, {%0,%1,%2,%3};"
                 : "+f"(d[0]), "+f"(d[1]), "+f"(d[2]), "+f"(d[3])
                 : "r"(a[0]), "r"(a[1]), "r"(a[2]), "r"(a[3]), "r"(b[0]), "r"(b[1]));
}
__device__ __forceinline__ void cpasync16(unsigned saddr, const void* g) {
    asm volatile("cp.async.cg.shared.global [%0], [%1], 16;" :: "r"(saddr), "l"(g));
}
__device__ __forceinline__ void cpcommit() { asm volatile("cp.async.commit_group;" ::: "memory"); }
template<int N> __device__ __forceinline__ void cpwait() {
    asm volatile("cp.async.wait_group %0;" :: "n"(N) : "memory");
}
__device__ __forceinline__ unsigned pk_h2(float a, float b) {
    return (unsigned)__half_as_ushort(__float2half_rn(a))
         | ((unsigned)__half_as_ushort(__float2half_rn(b)) << 16);
}
__device__ __forceinline__ unsigned pkh2f(float a, float b) {
    __half2 h = __floats2half2_rn(a, b);
    return *(unsigned*)&h;
}

// ---------------------------------------------------------------------------
// k_pre: fused prologue. Block ranges:
//   [0, 4096)       foldw (x4 vectorized) — W_ih+W_hh -> g_WswF, W_hh -> g_Wsw0
//   [4096, 5120)    foldo (x4 vectorized) — W_out -> g_WoT tiles (k_out layout)
//   [5120, 5632)    bias  — g_bF / g_b0 (x0-folded)
//   [5632, 5760)    init  — h0 (fp16 tiled) + c0; 128 blocks x 8 units
// ---------------------------------------------------------------------------
__global__ void __launch_bounds__(256) k_pre(
    const float* __restrict__ z,
    const float* __restrict__ Wfch, const float* __restrict__ bfch,
    const float* __restrict__ Wfcc, const float* __restrict__ bfcc,
    const float* __restrict__ Wih,  const float* __restrict__ bih,
    const float* __restrict__ Whh,  const float* __restrict__ bhh,
    const float* __restrict__ x0,   const float* __restrict__ Wout)
{
    __shared__ float zs[128][33];
    __shared__ float Whs[8][33];
    __shared__ float Wcs[8][33];
    const int tid = threadIdx.x;
    const int blk = blockIdx.x;

    if (blk < 4096) {
        // ---- foldw, 4 consecutive k per thread ----
        int i = blk * 256 + tid;                          // 1,048,576
        int k4 = (i & 255) << 2, rr = (i >> 8) & 31, bx = i >> 13;
        int gate = rr >> 3, unit = rr & 7;
        int j = (gate << 10) + (bx << 3) + unit;
        float4 a4 = *(const float4*)(Wih + (size_t)j * HH + k4);
        float4 b4 = *(const float4*)(Whh + (size_t)j * HH + k4);
        int off = ((k4 >> 4) << 10) + (((gate << 1) + ((k4 >> 3) & 1)) << 7)
                + (unit << 4) + ((k4 & 7) << 1);
        uint2 vf, v0;
        vf.x = pkh2f(a4.x + b4.x, a4.y + b4.y);
        vf.y = pkh2f(a4.z + b4.z, a4.w + b4.w);
        v0.x = pkh2f(b4.x, b4.y);
        v0.y = pkh2f(b4.z, b4.w);
        *(uint2*)(g_WswF + (size_t)bx * 65536 + off) = vf;
        *(uint2*)(g_Wsw0 + (size_t)bx * 65536 + off) = v0;
    } else if (blk < 5120) {
        // ---- foldo: W_out -> [nb][ch] 8KB tiles [ck4][nt*2+kt][8x16B], x4 vec ----
        int i = (blk - 4096) * 256 + tid;                 // 262,144
        int k4 = (i & 255) << 2, o = i >> 8;
        int nb = o >> 6, nt = (o >> 3) & 7, r = o & 7;
        int ch = k4 >> 6, ck4 = (k4 >> 4) & 3, kt = (k4 >> 3) & 1, c = k4 & 7;
        float4 w4 = *(const float4*)(Wout + (size_t)o * HH + k4);
        int toff = (ck4 << 11) + (((nt << 1) + kt) << 7) + (r << 4) + (c << 1);
        uint2 v;
        v.x = pkh2f(w4.x, w4.y);
        v.y = pkh2f(w4.z, w4.w);
        *(uint2*)(g_WoT + (size_t)(nb * 16 + ch) * 8192 + toff) = v;
    } else if (blk < 5632) {
        // ---- bias ----
        int w    = ((blk - 5120) * 256 + tid) >> 5;
        int lane = tid & 31;
        int bx = w >> 5, lr = w & 31;
        int j  = (bx << 3) + (lr & 7) + ((lr >> 3) << 10);
        float s = 0.f;
        for (int k = lane; k < HH; k += 32) s += x0[k] * Wih[(size_t)j * HH + k];
        #pragma unroll
        for (int off = 16; off; off >>= 1) s += __shfl_down_sync(0xffffffffu, s, off);
        if (lane == 0) {
            float bf = bih[j] + bhh[j];
            g_bF[w] = bf;
            g_b0[w] = bf + s;
        }
    } else {
        // ---- init: block bb handles units [bb*8, bb*8+8) for all 128 batches ----
        int bb = blk - 5632;                              // 0..127
        const int b = tid & 127, ug = tid >> 7;
        float accH[4], accC[4];
        #pragma unroll
        for (int j = 0; j < 4; ++j) { accH[j] = 0.f; accC[j] = 0.f; }

        for (int kc = 0; kc < 16; ++kc) {
            #pragma unroll
            for (int tq = 0; tq < 16; ++tq) {
                int idx = tid + tq * 256;
                int br = idx >> 5, kk = idx & 31;
                zs[br][kk] = z[br * DIN + kc * 32 + kk];
            }
            {
                int ur = tid >> 5, kk = tid & 31;
                Whs[ur][kk] = Wfch[(size_t)(bb * 8 + ur) * DIN + kc * 32 + kk];
                Wcs[ur][kk] = Wfcc[(size_t)(bb * 8 + ur) * DIN + kc * 32 + kk];
            }
            __syncthreads();
            #pragma unroll 8
            for (int kk = 0; kk < 32; ++kk) {
                float zv = zs[b][kk];
                #pragma unroll
                for (int j = 0; j < 4; ++j) {
                    accH[j] += zv * Whs[ug * 4 + j][kk];
                    accC[j] += zv * Wcs[ug * 4 + j][kk];
                }
            }
            __syncthreads();
        }

        #pragma unroll
        for (int j = 0; j < 4; ++j) {
            int u = bb * 8 + ug * 4 + j;
            float hv = accH[j] + bfch[u];
            int ck = u >> 6, C = u & 63;
            int off = (((b >> 3) << 3) + (C >> 3)) * 128 + ((b & 7) << 4) + ((C & 7) << 1);
            *(__half*)(g_hT + (size_t)ck * 16384 + off) = __float2half_rn(hv);
            g_c0[b * HH + u] = accC[j] + bfcc[u];
        }
    }
}

// ---------------------------------------------------------------------------
// Persistent HMMA recurrence (R13-proven). 128 CTAs x 8 warps. fp16 W slice
// (64KB) in SMEM. h staged via cp.async, 16KB chunks, 4-deep ring, depth 2.
// SMEM: [0..128) b0s [128..256) bFs | 1024 W 64K | A ring 66560 + i*16384
// ---------------------------------------------------------------------------
#define S_W   1024
#define S_TOT 132096

__global__ void __launch_bounds__(NTHR, 1) k_steps_mma() {
    extern __shared__ unsigned char sm[];
    const unsigned sb = smem_u32(sm);
    const int tid = threadIdx.x, blk = blockIdx.x;
    const int w = tid >> 5, lane = tid & 31;
    const int q = lane & 3, gr = lane >> 2, ls = lane >> 3;
    float* b0s = (float*)(sm);
    float* bFs = (float*)(sm + 128);

    if (tid < 32) {
        b0s[tid] = g_b0[blk * 32 + tid];
        bFs[tid] = g_bF[blk * 32 + tid];
    }
    {   // W slice for step 0 (W_hh only)
        const uint4* src = (const uint4*)(g_Wsw0 + (size_t)blk * 65536);
        uint4* dst = (uint4*)(sm + S_W);
        for (int i = tid; i < 4096; i += NTHR) dst[i] = src[i];
    }
    float cst[2][2];
    {
        int m0 = (w << 4) + gr;
        float2 v0 = *(const float2*)(g_c0 + m0 * HH + (blk << 3) + (q << 1));
        float2 v1 = *(const float2*)(g_c0 + (m0 + 8) * HH + (blk << 3) + (q << 1));
        cst[0][0] = v0.x; cst[0][1] = v0.y;
        cst[1][0] = v1.x; cst[1][1] = v1.y;
    }
    __syncthreads();

    const unsigned aBase = (unsigned)(((w * 2 + (ls & 1)) * 8 + (ls >> 1)) * 128 + (lane & 7) * 16);
    const unsigned bBase = (unsigned)((((ls >> 1) * 2 + (ls & 1)) * 128) + (lane & 7) * 16);
    const int cpo = tid * 16;
    unsigned bufs[4] = {sb + 66560u, sb + 82944u, sb + 99328u, sb + 115712u};

    for (int t = 0; t < TT; ++t) {
        const unsigned char* hsrc = g_hT + (size_t)t * SLOT;

        // prologue: issue chunks 0,1,2
        #pragma unroll
        for (int c = 0; c < 3; ++c) {
            const unsigned char* src = hsrc + (size_t)c * 16384;
            #pragma unroll
            for (int j = 0; j < 4; ++j) cpasync16(bufs[c] + cpo + j * 4096, src + cpo + j * 4096);
            cpcommit();
        }

        float acc[4][4];
        #pragma unroll
        for (int a = 0; a < 4; ++a)
            #pragma unroll
            for (int b = 0; b < 4; ++b) acc[a][b] = 0.f;

        for (int i = 0; i < 16; ++i) {
            if (i <= 13) cpwait<2>(); else if (i == 14) cpwait<1>(); else cpwait<0>();
            __syncthreads();
            if (i < 13) {   // prefetch chunk i+3 into freed buffer
                const unsigned char* src = hsrc + (size_t)(i + 3) * 16384;
                unsigned buf = bufs[(i + 3) & 3];
                #pragma unroll
                for (int j = 0; j < 4; ++j) cpasync16(buf + cpo + j * 4096, src + cpo + j * 4096);
                cpcommit();
            }
            unsigned cur = bufs[i & 3];
            #pragma unroll
            for (int kk = 0; kk < 4; ++kk) {
                unsigned Ah[4];
                ldsm4(Ah, cur + aBase + kk * 256);
                int ckk = i * 4 + kk;
                #pragma unroll
                for (int gg = 0; gg < 2; ++gg) {
                    unsigned Bh[4];
                    ldsm4(Bh, sb + S_W + ckk * 1024 + gg * 512 + bBase);
                    mma16816(acc[2 * gg],     Ah, Bh);
                    mma16816(acc[2 * gg + 1], Ah, Bh + 2);
                }
            }
        }

        // epilogue: 4 gates of (b, u) live in this thread
        const float* bs = t ? bFs : b0s;
        unsigned char* hd = g_hT + (size_t)(t + 1) * SLOT + (size_t)(blk >> 3) * 16384;
        const int cb = blk & 7;
        #pragma unroll
        for (int r = 0; r < 2; ++r) {
            float hv[2];
            #pragma unroll
            for (int s = 0; s < 2; ++s) {
                int u = (q << 1) + s;
                int fi = r * 2 + s;
                float ig = acc[0][fi] + bs[u];
                float fg = acc[1][fi] + bs[8 + u];
                float gg = acc[2][fi] + bs[16 + u];
                float og = acc[3][fi] + bs[24 + u];
                float cn = sigf(fg) * cst[r][s] + sigf(ig) * tanhf(gg);
                cst[r][s] = cn;
                hv[s] = sigf(og) * tanhf(cn);
            }
            int toff = (((2 * w + r) << 3) + cb) * 128 + (gr << 4) + (q << 2);
            *(unsigned*)(hd + toff) = pk_h2(hv[0], hv[1]);
        }

        // global barrier (monotonic, replay-safe; all-thread fence -> release post)
        __threadfence();
        __syncthreads();
        if (tid == 0) {
            unsigned old;
            asm volatile("atom.release.gpu.global.add.u32 %0, [%1], %2;"
                         : "=r"(old) : "l"(&g_bar[t]), "r"(1u) : "memory");
            unsigned target = old - (old & (NBLK - 1)) + NBLK;
            unsigned v;
            do {
                asm volatile("ld.acquire.gpu.global.u32 %0, [%1];"
                             : "=r"(v) : "l"(&g_bar[t]) : "memory");
            } while ((int)(v - target) < 0);
        }
        __syncthreads();

        if (t == 0) {   // swap in folded weights for steps >= 1
            const uint4* src = (const uint4*)(g_WswF + (size_t)blk * 65536);
            uint4* dst = (uint4*)(sm + S_W);
            for (int i2 = tid; i2 < 4096; i2 += NTHR) dst[i2] = src[i2];
            __syncthreads();
        }
    }
}

// ---------------------------------------------------------------------------
// Output GEMM via cp.async staging (R13-proven). A fp16 from g_hT, B fp16 from
// g_WoT. 128x64 tiles, 2-deep ring (24KB/buf), occupancy 2.
// SMEM: bias 0..256 | buf0 1024 | buf1 25600  (A +0 16KB, B +16384 8KB)
// ---------------------------------------------------------------------------
#define KO_B0 1024
#define KO_B1 25600
#define SO_TOT 50176

__global__ void __launch_bounds__(256, 2) k_out_mma(const float* __restrict__ bout,
                                                    float* __restrict__ out) {
    extern __shared__ unsigned char sm[];
    const unsigned sb = smem_u32(sm);
    const int tid = threadIdx.x;
    const int w = tid >> 5, lane = tid & 31;
    const int q = lane & 3, gr = lane >> 2, ls = lane >> 3;
    const int nb = blockIdx.x, mb = blockIdx.y;
    float* bias_s = (float*)(sm);
    if (tid < 64) bias_s[tid] = bout[nb * 64 + tid];

    const unsigned aBase = (unsigned)(((w * 2 + (ls & 1)) * 8 + (ls >> 1)) * 128 + (lane & 7) * 16);
    const unsigned bBase = (unsigned)((((ls >> 1) * 2 + (ls & 1)) * 128) + (lane & 7) * 16);
    const int cpo = tid * 16;
    const int cpo2 = tid * 32;   // B chunk: 8KB over 256 threads = 32B each
    const unsigned char* Asrc = g_hT + (size_t)(mb + 1) * SLOT;
    const unsigned char* Bsrc = g_WoT + (size_t)nb * 16 * 8192;

    auto issue = [&](int ch, unsigned buf) {
        const unsigned char* a = Asrc + (size_t)ch * 16384;
        #pragma unroll
        for (int j = 0; j < 4; ++j) cpasync16(buf + cpo + j * 4096, a + cpo + j * 4096);
        const unsigned char* bsc = Bsrc + (size_t)ch * 8192;
        cpasync16(buf + 16384 + cpo2,      bsc + cpo2);
        cpasync16(buf + 16384 + cpo2 + 16, bsc + cpo2 + 16);
        cpcommit();
    };

    unsigned cur = sb + KO_B0, oth = sb + KO_B1;
    issue(0, cur);
    issue(1, oth);

    float acc[8][4];
    #pragma unroll
    for (int a = 0; a < 8; ++a)
        #pragma unroll
        for (int b = 0; b < 4; ++b) acc[a][b] = 0.f;

    for (int i = 0; i < 16; ++i) {
        if (i < 15) cpwait<1>(); else cpwait<0>();
        __syncthreads();
        #pragma unroll
        for (int kk = 0; kk < 4; ++kk) {
            unsigned Ah[4];
            ldsm4(Ah, cur + aBase + kk * 256);
            #pragma unroll
            for (int gg = 0; gg < 4; ++gg) {
                unsigned Bh[4];
                ldsm4(Bh, cur + 16384 + kk * 2048 + gg * 512 + bBase);
                mma16816(acc[2 * gg],     Ah, Bh);
                mma16816(acc[2 * gg + 1], Ah, Bh + 2);
            }
        }
        __syncthreads();
        if (i < 14) issue(i + 2, cur);
        unsigned tmp = cur; cur = oth; oth = tmp;
    }

    // epilogue: bias + LeakyReLU, float2 stores
    #pragma unroll
    for (int nt = 0; nt < 8; ++nt) {
        int o0 = nb * 64 + nt * 8 + (q << 1);
        float bo0 = bias_s[nt * 8 + (q << 1)];
        float bo1 = bias_s[nt * 8 + (q << 1) + 1];
        #pragma unroll
        for (int r = 0; r < 2; ++r) {
            int m = mb * 128 + (w << 4) + gr + (r << 3);
            int tt = m >> 7, b = m & 127;
            float x0 = acc[nt][r * 2]     + bo0;
            float x1 = acc[nt][r * 2 + 1] + bo1;
            float2 v;
            v.x = x0 >= 0.f ? x0 : 0.2f * x0;
            v.y = x1 >= 0.f ? x1 : 0.2f * x1;
            *(float2*)(out + (size_t)b * (TT * OO) + (size_t)tt * OO + o0) = v;
        }
    }
}

// ---------------------------------------------------------------------------
extern "C" void kernel_launch(void* const* d_in, const int* in_sizes, int n_in,
                              void* d_out, int out_size) {
    const float* z      = (const float*)d_in[0];
    const float* W_fc_h = (const float*)d_in[2];
    const float* b_fc_h = (const float*)d_in[3];
    const float* W_fc_c = (const float*)d_in[4];
    const float* b_fc_c = (const float*)d_in[5];
    const float* W_ih   = (const float*)d_in[6];
    const float* b_ih   = (const float*)d_in[7];
    const float* W_hh   = (const float*)d_in[8];
    const float* b_hh   = (const float*)d_in[9];
    const float* x0     = (const float*)d_in[10];
    const float* W_out  = (const float*)d_in[11];
    const float* b_out  = (const float*)d_in[12];
    float* out = (float*)d_out;

    k_pre<<<5760, 256>>>(z, W_fc_h, b_fc_h, W_fc_c, b_fc_c,
                         W_ih, b_ih, W_hh, b_hh, x0, W_out);

    cudaFuncSetAttribute(k_steps_mma, cudaFuncAttributeMaxDynamicSharedMemorySize, S_TOT);
    k_steps_mma<<<NBLK, NTHR, S_TOT>>>();

    cudaFuncSetAttribute(k_out_mma, cudaFuncAttributeMaxDynamicSharedMemorySize, SO_TOT);
    k_out_mma<<<dim3(16, 256), 256, SO_TOT>>>(b_out, out);
}